// round 1
// baseline (speedup 1.0000x reference)
#include <cuda_runtime.h>

#define N_NODES 100000
#define N_EDGES 1600000
#define F_IN 128
#define H1 64
#define H2 32

// Scratch (allocation-free rule: __device__ globals)
__device__ float g_xw1[(size_t)N_NODES * H1];  // X @ W1            25.6 MB
__device__ float g_a1 [(size_t)N_NODES * H1];  // A @ (X W1)        25.6 MB
__device__ float g_h2 [(size_t)N_NODES * H2];  // relu(a1) @ W2     12.8 MB

__device__ __forceinline__ void red_add_v4(float* p, float4 v) {
    asm volatile("red.global.add.v4.f32 [%0], {%1, %2, %3, %4};"
                 :: "l"(p), "f"(v.x), "f"(v.y), "f"(v.z), "f"(v.w)
                 : "memory");
}

// Zero the layer-1 accumulator and the output (harness poisons d_out).
__global__ __launch_bounds__(256) void zero_kernel(float4* __restrict__ out4) {
    unsigned i = blockIdx.x * 256u + threadIdx.x;
    float4 z = make_float4(0.f, 0.f, 0.f, 0.f);
    if (i < (N_NODES * H1) / 4) reinterpret_cast<float4*>(g_a1)[i] = z;
    if (i < (N_NODES * H2) / 4) out4[i] = z;
}

// XW1 = X[100000,128] @ W1[128,64]. 16 rows/block, 16 threads/row (4 cols each).
__global__ __launch_bounds__(256) void gemm1_kernel(const float* __restrict__ X,
                                                    const float* __restrict__ W1) {
    __shared__ float sW[F_IN * H1];       // 32 KB
    __shared__ float sX[16][F_IN + 4];    // padded vs bank conflicts
    int tid = threadIdx.x;
    for (int i = tid; i < F_IN * H1; i += 256) sW[i] = W1[i];
    int row0 = blockIdx.x * 16;
    for (int i = tid; i < 16 * F_IN; i += 256) {
        int r = i >> 7, k = i & 127;
        int row = row0 + r;
        sX[r][k] = (row < N_NODES) ? X[(size_t)row * F_IN + k] : 0.f;
    }
    __syncthreads();
    int r  = tid >> 4;     // 0..15
    int cg = tid & 15;     // col group: cols cg*4 .. cg*4+3
    float4 acc = make_float4(0.f, 0.f, 0.f, 0.f);
#pragma unroll
    for (int k = 0; k < F_IN; k++) {
        float xv = sX[r][k];
        float4 w = *reinterpret_cast<const float4*>(&sW[k * H1 + cg * 4]);
        acc.x = fmaf(xv, w.x, acc.x);
        acc.y = fmaf(xv, w.y, acc.y);
        acc.z = fmaf(xv, w.z, acc.z);
        acc.w = fmaf(xv, w.w, acc.w);
    }
    int row = row0 + r;
    if (row < N_NODES)
        *reinterpret_cast<float4*>(&g_xw1[(size_t)row * H1 + cg * 4]) = acc;
}

// a1[dst] += w * xw1[src], 16 lanes/edge, float4 per lane, vector red.
__global__ __launch_bounds__(256) void scatter1_kernel(const float* __restrict__ ew,
                                                       const int*   __restrict__ src,
                                                       const int*   __restrict__ dst) {
    unsigned gid = blockIdx.x * 256u + threadIdx.x;
    unsigned e = gid >> 4;
    if (e >= N_EDGES) return;
    int lane = gid & 15;
    int s = src[e], d = dst[e];
    float w = ew[e];
    float4 v = *reinterpret_cast<const float4*>(&g_xw1[(size_t)s * H1 + lane * 4]);
    v.x *= w; v.y *= w; v.z *= w; v.w *= w;
    red_add_v4(&g_a1[(size_t)d * H1 + lane * 4], v);
}

// h2 = relu(a1) @ W2[64,32]. 32 rows/block, 8 threads/row (4 cols each).
__global__ __launch_bounds__(256) void gemm2_kernel(const float* __restrict__ W2) {
    __shared__ float sW[H1 * H2];        // 8 KB
    __shared__ float sX[32][H1 + 4];
    int tid = threadIdx.x;
    for (int i = tid; i < H1 * H2; i += 256) sW[i] = W2[i];
    int row0 = blockIdx.x * 32;
    for (int i = tid; i < 32 * H1; i += 256) {
        int r = i >> 6, k = i & 63;
        int row = row0 + r;
        float v = (row < N_NODES) ? g_a1[(size_t)row * H1 + k] : 0.f;
        sX[r][k] = fmaxf(v, 0.f);        // fused ReLU
    }
    __syncthreads();
    int r  = tid >> 3;    // 0..31
    int cg = tid & 7;     // cols cg*4 .. cg*4+3
    float4 acc = make_float4(0.f, 0.f, 0.f, 0.f);
#pragma unroll
    for (int k = 0; k < H1; k++) {
        float xv = sX[r][k];
        float4 w = *reinterpret_cast<const float4*>(&sW[k * H2 + cg * 4]);
        acc.x = fmaf(xv, w.x, acc.x);
        acc.y = fmaf(xv, w.y, acc.y);
        acc.z = fmaf(xv, w.z, acc.z);
        acc.w = fmaf(xv, w.w, acc.w);
    }
    int row = row0 + r;
    if (row < N_NODES)
        *reinterpret_cast<float4*>(&g_h2[(size_t)row * H2 + cg * 4]) = acc;
}

// out[dst] += w * h2[src], 8 lanes/edge, float4 per lane.
__global__ __launch_bounds__(256) void scatter2_kernel(const float* __restrict__ ew,
                                                       const int*   __restrict__ src,
                                                       const int*   __restrict__ dst,
                                                       float* __restrict__ out) {
    unsigned gid = blockIdx.x * 256u + threadIdx.x;
    unsigned e = gid >> 3;
    if (e >= N_EDGES) return;
    int lane = gid & 7;
    int s = src[e], d = dst[e];
    float w = ew[e];
    float4 v = *reinterpret_cast<const float4*>(&g_h2[(size_t)s * H2 + lane * 4]);
    v.x *= w; v.y *= w; v.z *= w; v.w *= w;
    red_add_v4(&out[(size_t)d * H2 + lane * 4], v);
}

extern "C" void kernel_launch(void* const* d_in, const int* in_sizes, int n_in,
                              void* d_out, int out_size) {
    const float* features = (const float*)d_in[0];
    const float* ew       = (const float*)d_in[1];
    const float* W1       = (const float*)d_in[2];
    const float* W2       = (const float*)d_in[3];
    const int*   src      = (const int*)d_in[4];
    const int*   dst      = (const int*)d_in[5];
    float*       out      = (float*)d_out;

    // zero g_a1 (1.6M float4) and d_out (0.8M float4)
    zero_kernel<<<(N_NODES * H1 / 4 + 255) / 256, 256>>>((float4*)out);

    gemm1_kernel<<<(N_NODES + 15) / 16, 256>>>(features, W1);

    scatter1_kernel<<<(N_EDGES * 16 + 255) / 256, 256>>>(ew, src, dst);

    gemm2_kernel<<<(N_NODES + 31) / 32, 256>>>(W2);

    scatter2_kernel<<<(N_EDGES * 8 + 255) / 256, 256>>>(ew, src, dst, out);
}

// round 2
// speedup vs baseline: 1.2464x; 1.2464x over previous
#include <cuda_runtime.h>

typedef unsigned long long ull;

#define N_NODES 100000
#define N_EDGES 1600000
#define F_IN 128
#define H1 64
#define H2 32
#define SCAN_B 391            // ceil(N_NODES/256)

// ---------------- scratch (__device__ globals; no allocation allowed) ------
__device__ float g_xw1[(size_t)N_NODES * H1];   // X @ W1
__device__ float g_a1 [(size_t)N_NODES * H1];   // relu(A @ XW1)  (relu fused)
__device__ float g_h2 [(size_t)N_NODES * H2];   // a1 @ W2
__device__ int   g_deg[N_NODES];
__device__ int   g_off[N_NODES + 1];
__device__ int   g_cur[N_NODES];
__device__ int   g_bsum[512];
__device__ int   g_srcs[N_EDGES];               // src permuted into dst-grouped order
__device__ float g_ws  [N_EDGES];               // weights, same order

// ---------------- f32x2 helpers (Blackwell packed fp32 pipe) ---------------
__device__ __forceinline__ void fma2(ull& d, ull a, ull b) {
    asm("fma.rn.f32x2 %0, %1, %2, %0;" : "+l"(d) : "l"(a), "l"(b));
}
__device__ __forceinline__ ull bcast2(float w) {
    ull r; asm("mov.b64 %0, {%1, %1};" : "=l"(r) : "f"(w)); return r;
}

// ---------------- CSR build ------------------------------------------------
__global__ __launch_bounds__(256) void zero_deg_kernel() {
    int i = blockIdx.x * 256 + threadIdx.x;
    if (i < N_NODES) g_deg[i] = 0;
}

__global__ __launch_bounds__(256) void count_kernel(const int* __restrict__ dst) {
    int e = blockIdx.x * 256 + threadIdx.x;
    if (e < N_EDGES) atomicAdd(&g_deg[dst[e]], 1);
}

__global__ __launch_bounds__(256) void scan1_kernel() {
    __shared__ int s[256];
    int t = threadIdx.x;
    int i = blockIdx.x * 256 + t;
    int v = (i < N_NODES) ? g_deg[i] : 0;
    s[t] = v; __syncthreads();
#pragma unroll
    for (int d = 1; d < 256; d <<= 1) {
        int x = (t >= d) ? s[t - d] : 0;
        __syncthreads();
        s[t] += x;
        __syncthreads();
    }
    if (i < N_NODES) g_off[i] = s[t];            // in-block inclusive scan
    if (t == 255) g_bsum[blockIdx.x] = s[255];   // block total
}

__global__ __launch_bounds__(512) void scan2_kernel() {
    __shared__ int s[512];
    int t = threadIdx.x;
    int v = (t < SCAN_B) ? g_bsum[t] : 0;
    s[t] = v; __syncthreads();
#pragma unroll
    for (int d = 1; d < 512; d <<= 1) {
        int x = (t >= d) ? s[t - d] : 0;
        __syncthreads();
        s[t] += x;
        __syncthreads();
    }
    if (t < SCAN_B) g_bsum[t] = s[t] - v;        // exclusive block offsets
}

__global__ __launch_bounds__(256) void scan3_kernel() {
    int i = blockIdx.x * 256 + threadIdx.x;
    if (i < N_NODES) {
        int off = g_off[i] - g_deg[i] + g_bsum[blockIdx.x];  // global exclusive
        g_off[i] = off;
        g_cur[i] = off;
    }
    if (i == 0) g_off[N_NODES] = N_EDGES;
}

__global__ __launch_bounds__(256) void fill_kernel(const float* __restrict__ ew,
                                                   const int*   __restrict__ src,
                                                   const int*   __restrict__ dst) {
    int e = blockIdx.x * 256 + threadIdx.x;
    if (e >= N_EDGES) return;
    int d = dst[e];
    int p = atomicAdd(&g_cur[d], 1);
    g_srcs[p] = src[e];
    g_ws[p]   = ew[e];
}

// ---------------- GEMM 1: xw1 = X[100k,128] @ W1[128,64] -------------------
// block: 256 rows x 64 cols, 256 threads, thread tile 8 rows x 8 cols, f32x2.
#define G1_KC 16
#define G1_XP 258          // sXt row pitch (even -> 8B-aligned row pairs)
__global__ __launch_bounds__(256) void gemm1_kernel(const float* __restrict__ X,
                                                    const float* __restrict__ W1) {
    __shared__ float sXt[G1_KC * G1_XP];   // [k][row]  (k-major => row-pair LDS.64)
    __shared__ ull   sW2[G1_KC * H1];      // [k][col] duplicated {w,w}
    int tid  = threadIdx.x;
    int row0 = blockIdx.x * 256;
    int tx   = tid & 7;        // cols tx*8 .. tx*8+7
    int ty   = tid >> 3;       // rows ty*8 .. ty*8+7 (4 row-pairs)

    ull acc[4][8];
#pragma unroll
    for (int p = 0; p < 4; p++)
#pragma unroll
        for (int c = 0; c < 8; c++) acc[p][c] = 0ull;

    for (int kc = 0; kc < F_IN; kc += G1_KC) {
        // stage X chunk transposed: 256 rows x 16 k
#pragma unroll
        for (int j = 0; j < 4; j++) {
            int i = tid + j * 256;             // 0..1023 float4 loads
            int r = i >> 2, kq = i & 3;
            int row = row0 + r;
            float4 v = make_float4(0.f, 0.f, 0.f, 0.f);
            if (row < N_NODES)
                v = *reinterpret_cast<const float4*>(&X[(size_t)row * F_IN + kc + kq * 4]);
            sXt[(kq * 4 + 0) * G1_XP + r] = v.x;
            sXt[(kq * 4 + 1) * G1_XP + r] = v.y;
            sXt[(kq * 4 + 2) * G1_XP + r] = v.z;
            sXt[(kq * 4 + 3) * G1_XP + r] = v.w;
        }
        // stage W chunk duplicated
#pragma unroll
        for (int j = 0; j < 4; j++) {
            int i = tid + j * 256;             // 0..1023
            int k = i >> 6, c = i & 63;
            sW2[k * H1 + c] = bcast2(W1[(size_t)(kc + k) * H1 + c]);
        }
        __syncthreads();
#pragma unroll
        for (int k = 0; k < G1_KC; k++) {
            const ull* xk = reinterpret_cast<const ull*>(&sXt[k * G1_XP + ty * 8]);
            ull x0 = xk[0], x1 = xk[1], x2 = xk[2], x3 = xk[3];
            const ull* wk = &sW2[k * H1 + tx * 8];
#pragma unroll
            for (int c = 0; c < 8; c++) {
                ull wb = wk[c];
                fma2(acc[0][c], x0, wb);
                fma2(acc[1][c], x1, wb);
                fma2(acc[2][c], x2, wb);
                fma2(acc[3][c], x3, wb);
            }
        }
        __syncthreads();
    }
    // epilogue: unpack pairs, store 8 floats per row
#pragma unroll
    for (int p = 0; p < 4; p++) {
#pragma unroll
        for (int h = 0; h < 2; h++) {
            int row = row0 + ty * 8 + 2 * p + h;
            if (row < N_NODES) {
                float o[8];
#pragma unroll
                for (int c = 0; c < 8; c++) {
                    unsigned v = h ? (unsigned)(acc[p][c] >> 32) : (unsigned)acc[p][c];
                    o[c] = __uint_as_float(v);
                }
                float4* dst4 = reinterpret_cast<float4*>(&g_xw1[(size_t)row * H1 + tx * 8]);
                dst4[0] = make_float4(o[0], o[1], o[2], o[3]);
                dst4[1] = make_float4(o[4], o[5], o[6], o[7]);
            }
        }
    }
}

// ---------------- aggregation 1: a1 = relu(sum_e w*xw1[src]) ---------------
// one warp per dst node; lane owns 2 features (float2), edges streamed from CSR
__global__ __launch_bounds__(256) void agg1_kernel() {
    int node = blockIdx.x * 8 + (threadIdx.x >> 5);
    if (node >= N_NODES) return;
    int lane = threadIdx.x & 31;
    int p = g_off[node], e = g_off[node + 1];
    float2 acc = make_float2(0.f, 0.f);
#pragma unroll 2
    for (; p < e; p++) {
        int   s = g_srcs[p];
        float w = g_ws[p];
        float2 v = *reinterpret_cast<const float2*>(&g_xw1[(size_t)s * H1 + lane * 2]);
        acc.x = fmaf(w, v.x, acc.x);
        acc.y = fmaf(w, v.y, acc.y);
    }
    acc.x = fmaxf(acc.x, 0.f);
    acc.y = fmaxf(acc.y, 0.f);
    *reinterpret_cast<float2*>(&g_a1[(size_t)node * H1 + lane * 2]) = acc;
}

// ---------------- GEMM 2: h2 = a1[100k,64] @ W2[64,32] ---------------------
// block: 256 rows x 32 cols, 128 threads, thread tile 8 rows x 8 cols, f32x2.
#define G2_KC 16
__global__ __launch_bounds__(128) void gemm2_kernel(const float* __restrict__ W2) {
    __shared__ float sXt[G2_KC * G1_XP];
    __shared__ ull   sW2[G2_KC * H2];
    int tid  = threadIdx.x;
    int row0 = blockIdx.x * 256;
    int tx   = tid & 3;        // cols tx*8 .. +7
    int ty   = tid >> 2;       // rows ty*8 .. +7

    ull acc[4][8];
#pragma unroll
    for (int p = 0; p < 4; p++)
#pragma unroll
        for (int c = 0; c < 8; c++) acc[p][c] = 0ull;

    for (int kc = 0; kc < H1; kc += G2_KC) {
#pragma unroll
        for (int j = 0; j < 8; j++) {
            int i = tid + j * 128;             // 0..1023 float4 loads
            int r = i >> 2, kq = i & 3;
            int row = row0 + r;
            float4 v = make_float4(0.f, 0.f, 0.f, 0.f);
            if (row < N_NODES)
                v = *reinterpret_cast<const float4*>(&g_a1[(size_t)row * H1 + kc + kq * 4]);
            sXt[(kq * 4 + 0) * G1_XP + r] = v.x;
            sXt[(kq * 4 + 1) * G1_XP + r] = v.y;
            sXt[(kq * 4 + 2) * G1_XP + r] = v.z;
            sXt[(kq * 4 + 3) * G1_XP + r] = v.w;
        }
#pragma unroll
        for (int j = 0; j < 4; j++) {
            int i = tid + j * 128;             // 0..511
            int k = i >> 5, c = i & 31;
            sW2[k * H2 + c] = bcast2(W2[(size_t)(kc + k) * H2 + c]);
        }
        __syncthreads();
#pragma unroll
        for (int k = 0; k < G2_KC; k++) {
            const ull* xk = reinterpret_cast<const ull*>(&sXt[k * G1_XP + ty * 8]);
            ull x0 = xk[0], x1 = xk[1], x2 = xk[2], x3 = xk[3];
            const ull* wk = &sW2[k * H2 + tx * 8];
#pragma unroll
            for (int c = 0; c < 8; c++) {
                ull wb = wk[c];
                fma2(acc[0][c], x0, wb);
                fma2(acc[1][c], x1, wb);
                fma2(acc[2][c], x2, wb);
                fma2(acc[3][c], x3, wb);
            }
        }
        __syncthreads();
    }
#pragma unroll
    for (int p = 0; p < 4; p++) {
#pragma unroll
        for (int h = 0; h < 2; h++) {
            int row = row0 + ty * 8 + 2 * p + h;
            if (row < N_NODES) {
                float o[8];
#pragma unroll
                for (int c = 0; c < 8; c++) {
                    unsigned v = h ? (unsigned)(acc[p][c] >> 32) : (unsigned)acc[p][c];
                    o[c] = __uint_as_float(v);
                }
                float4* dst4 = reinterpret_cast<float4*>(&g_h2[(size_t)row * H2 + tx * 8]);
                dst4[0] = make_float4(o[0], o[1], o[2], o[3]);
                dst4[1] = make_float4(o[4], o[5], o[6], o[7]);
            }
        }
    }
}

// ---------------- aggregation 2: out = sum_e w*h2[src] ---------------------
// one warp per dst node; lane owns 1 output feature
__global__ __launch_bounds__(256) void agg2_kernel(float* __restrict__ out) {
    int node = blockIdx.x * 8 + (threadIdx.x >> 5);
    if (node >= N_NODES) return;
    int lane = threadIdx.x & 31;
    int p = g_off[node], e = g_off[node + 1];
    float acc = 0.f;
#pragma unroll 2
    for (; p < e; p++) {
        int   s = g_srcs[p];
        float w = g_ws[p];
        acc = fmaf(w, g_h2[(size_t)s * H2 + lane], acc);
    }
    out[(size_t)node * H2 + lane] = acc;
}

// ---------------- launch ---------------------------------------------------
extern "C" void kernel_launch(void* const* d_in, const int* in_sizes, int n_in,
                              void* d_out, int out_size) {
    const float* features = (const float*)d_in[0];
    const float* ew       = (const float*)d_in[1];
    const float* W1       = (const float*)d_in[2];
    const float* W2       = (const float*)d_in[3];
    const int*   src      = (const int*)d_in[4];
    const int*   dst      = (const int*)d_in[5];
    float*       out      = (float*)d_out;

    zero_deg_kernel<<<SCAN_B, 256>>>();
    count_kernel<<<(N_EDGES + 255) / 256, 256>>>(dst);
    scan1_kernel<<<SCAN_B, 256>>>();
    scan2_kernel<<<1, 512>>>();
    scan3_kernel<<<SCAN_B, 256>>>();
    fill_kernel<<<(N_EDGES + 255) / 256, 256>>>(ew, src, dst);

    gemm1_kernel<<<(N_NODES + 255) / 256, 256>>>(features, W1);
    agg1_kernel<<<(N_NODES + 7) / 8, 256>>>();
    gemm2_kernel<<<(N_NODES + 255) / 256, 128>>>(W2);
    agg2_kernel<<<(N_NODES + 7) / 8, 256>>>(out);
}

// round 3
// speedup vs baseline: 1.3936x; 1.1181x over previous
#include <cuda_runtime.h>

typedef unsigned long long ull;

#define N_NODES 100000
#define N_EDGES 1600000
#define F_IN 128
#define H1 64
#define H2 32
#define SCAN_B 391            // ceil(N_NODES/256)

// ---------------- scratch (__device__ globals; no allocation allowed) ------
__device__ float g_xw1[(size_t)N_NODES * H1];   // X @ W1
__device__ float g_a1 [(size_t)N_NODES * H1];   // relu(A @ XW1)
__device__ float g_h2 [(size_t)N_NODES * H2];   // a1 @ W2
__device__ int   g_deg[N_NODES];
__device__ int   g_off[N_NODES + 1];
__device__ int   g_cur[N_NODES];
__device__ int   g_bsum[512];
__device__ int2  g_edge[N_EDGES];               // (src, w_bits) grouped by dst

// ---------------- f32x2 helpers (Blackwell packed fp32 pipe) ---------------
__device__ __forceinline__ void fma2(ull& d, ull a, ull b) {
    asm("fma.rn.f32x2 %0, %1, %2, %0;" : "+l"(d) : "l"(a), "l"(b));
}
__device__ __forceinline__ ull bcast2(float w) {
    ull r; asm("mov.b64 %0, {%1, %1};" : "=l"(r) : "f"(w)); return r;
}

// ---------------- CSR build ------------------------------------------------
__global__ __launch_bounds__(256) void zero_deg_kernel() {
    int i = blockIdx.x * 256 + threadIdx.x;
    if (i < N_NODES) g_deg[i] = 0;
}

__global__ __launch_bounds__(256) void count_kernel(const int* __restrict__ dst) {
    int e = blockIdx.x * 256 + threadIdx.x;
    if (e < N_EDGES) atomicAdd(&g_deg[dst[e]], 1);   // RED (no return)
}

__global__ __launch_bounds__(256) void scan1_kernel() {
    __shared__ int s[256];
    int t = threadIdx.x;
    int i = blockIdx.x * 256 + t;
    int v = (i < N_NODES) ? g_deg[i] : 0;
    s[t] = v; __syncthreads();
#pragma unroll
    for (int d = 1; d < 256; d <<= 1) {
        int x = (t >= d) ? s[t - d] : 0;
        __syncthreads();
        s[t] += x;
        __syncthreads();
    }
    if (i < N_NODES) g_off[i] = s[t];            // in-block inclusive scan
    if (t == 255) g_bsum[blockIdx.x] = s[255];   // block total
}

__global__ __launch_bounds__(512) void scan2_kernel() {
    __shared__ int s[512];
    int t = threadIdx.x;
    int v = (t < SCAN_B) ? g_bsum[t] : 0;
    s[t] = v; __syncthreads();
#pragma unroll
    for (int d = 1; d < 512; d <<= 1) {
        int x = (t >= d) ? s[t - d] : 0;
        __syncthreads();
        s[t] += x;
        __syncthreads();
    }
    if (t < SCAN_B) g_bsum[t] = s[t] - v;        // exclusive block offsets
}

__global__ __launch_bounds__(256) void scan3_kernel() {
    int i = blockIdx.x * 256 + threadIdx.x;
    if (i < N_NODES) {
        int off = g_off[i] - g_deg[i] + g_bsum[blockIdx.x];  // global exclusive
        g_off[i] = off;
        g_cur[i] = off;
    }
    if (i == 0) g_off[N_NODES] = N_EDGES;
}

__global__ __launch_bounds__(256) void fill_kernel(const float* __restrict__ ew,
                                                   const int*   __restrict__ src,
                                                   const int*   __restrict__ dst) {
    int e = blockIdx.x * 256 + threadIdx.x;
    if (e >= N_EDGES) return;
    int d = dst[e];
    int p = atomicAdd(&g_cur[d], 1);
    g_edge[p] = make_int2(src[e], __float_as_int(ew[e]));
}

// ---------------- GEMM 1: xw1 = X[100k,128] @ W1[128,64] -------------------
#define G1_KC 16
#define G1_XP 258
__global__ __launch_bounds__(256) void gemm1_kernel(const float* __restrict__ X,
                                                    const float* __restrict__ W1) {
    __shared__ float sXt[G1_KC * G1_XP];   // [k][row]
    __shared__ ull   sW2[G1_KC * H1];      // [k][col] duplicated {w,w}
    int tid  = threadIdx.x;
    int row0 = blockIdx.x * 256;
    int tx   = tid & 7;
    int ty   = tid >> 3;

    ull acc[4][8];
#pragma unroll
    for (int p = 0; p < 4; p++)
#pragma unroll
        for (int c = 0; c < 8; c++) acc[p][c] = 0ull;

    for (int kc = 0; kc < F_IN; kc += G1_KC) {
#pragma unroll
        for (int j = 0; j < 4; j++) {
            int i = tid + j * 256;
            int r = i >> 2, kq = i & 3;
            int row = row0 + r;
            float4 v = make_float4(0.f, 0.f, 0.f, 0.f);
            if (row < N_NODES)
                v = *reinterpret_cast<const float4*>(&X[(size_t)row * F_IN + kc + kq * 4]);
            sXt[(kq * 4 + 0) * G1_XP + r] = v.x;
            sXt[(kq * 4 + 1) * G1_XP + r] = v.y;
            sXt[(kq * 4 + 2) * G1_XP + r] = v.z;
            sXt[(kq * 4 + 3) * G1_XP + r] = v.w;
        }
#pragma unroll
        for (int j = 0; j < 4; j++) {
            int i = tid + j * 256;
            int k = i >> 6, c = i & 63;
            sW2[k * H1 + c] = bcast2(W1[(size_t)(kc + k) * H1 + c]);
        }
        __syncthreads();
#pragma unroll
        for (int k = 0; k < G1_KC; k++) {
            const ull* xk = reinterpret_cast<const ull*>(&sXt[k * G1_XP + ty * 8]);
            ull x0 = xk[0], x1 = xk[1], x2 = xk[2], x3 = xk[3];
            const ull* wk = &sW2[k * H1 + tx * 8];
#pragma unroll
            for (int c = 0; c < 8; c++) {
                ull wb = wk[c];
                fma2(acc[0][c], x0, wb);
                fma2(acc[1][c], x1, wb);
                fma2(acc[2][c], x2, wb);
                fma2(acc[3][c], x3, wb);
            }
        }
        __syncthreads();
    }
#pragma unroll
    for (int p = 0; p < 4; p++) {
#pragma unroll
        for (int h = 0; h < 2; h++) {
            int row = row0 + ty * 8 + 2 * p + h;
            if (row < N_NODES) {
                float o[8];
#pragma unroll
                for (int c = 0; c < 8; c++) {
                    unsigned v = h ? (unsigned)(acc[p][c] >> 32) : (unsigned)acc[p][c];
                    o[c] = __uint_as_float(v);
                }
                float4* dst4 = reinterpret_cast<float4*>(&g_xw1[(size_t)row * H1 + tx * 8]);
                dst4[0] = make_float4(o[0], o[1], o[2], o[3]);
                dst4[1] = make_float4(o[4], o[5], o[6], o[7]);
            }
        }
    }
}

// ---------------- aggregation 1: a1 = relu(sum_e w*xw1[src]) ---------------
// warp per dst node; lane owns 2 features; 4-edge unroll, 2 acc chains
__global__ __launch_bounds__(256) void agg1_kernel() {
    int node = blockIdx.x * 8 + (threadIdx.x >> 5);
    if (node >= N_NODES) return;
    int lane = threadIdx.x & 31;
    int p = g_off[node], e = g_off[node + 1];
    float2 a0 = make_float2(0.f, 0.f), a1v = make_float2(0.f, 0.f);
    for (; p + 4 <= e; p += 4) {
        int2 r0 = g_edge[p + 0];
        int2 r1 = g_edge[p + 1];
        int2 r2 = g_edge[p + 2];
        int2 r3 = g_edge[p + 3];
        float2 v0 = *reinterpret_cast<const float2*>(&g_xw1[(size_t)r0.x * H1 + lane * 2]);
        float2 v1 = *reinterpret_cast<const float2*>(&g_xw1[(size_t)r1.x * H1 + lane * 2]);
        float2 v2 = *reinterpret_cast<const float2*>(&g_xw1[(size_t)r2.x * H1 + lane * 2]);
        float2 v3 = *reinterpret_cast<const float2*>(&g_xw1[(size_t)r3.x * H1 + lane * 2]);
        float w0 = __int_as_float(r0.y), w1 = __int_as_float(r1.y);
        float w2 = __int_as_float(r2.y), w3 = __int_as_float(r3.y);
        a0.x  = fmaf(w0, v0.x, a0.x);  a0.y  = fmaf(w0, v0.y, a0.y);
        a1v.x = fmaf(w1, v1.x, a1v.x); a1v.y = fmaf(w1, v1.y, a1v.y);
        a0.x  = fmaf(w2, v2.x, a0.x);  a0.y  = fmaf(w2, v2.y, a0.y);
        a1v.x = fmaf(w3, v3.x, a1v.x); a1v.y = fmaf(w3, v3.y, a1v.y);
    }
    for (; p < e; p++) {
        int2 r = g_edge[p];
        float w = __int_as_float(r.y);
        float2 v = *reinterpret_cast<const float2*>(&g_xw1[(size_t)r.x * H1 + lane * 2]);
        a0.x = fmaf(w, v.x, a0.x);
        a0.y = fmaf(w, v.y, a0.y);
    }
    float2 acc;
    acc.x = fmaxf(a0.x + a1v.x, 0.f);
    acc.y = fmaxf(a0.y + a1v.y, 0.f);
    *reinterpret_cast<float2*>(&g_a1[(size_t)node * H1 + lane * 2]) = acc;
}

// ---------------- GEMM 2: h2 = a1[100k,64] @ W2[64,32] ---------------------
#define G2_KC 16
__global__ __launch_bounds__(128) void gemm2_kernel(const float* __restrict__ W2) {
    __shared__ float sXt[G2_KC * G1_XP];
    __shared__ ull   sW2[G2_KC * H2];
    int tid  = threadIdx.x;
    int row0 = blockIdx.x * 256;
    int tx   = tid & 3;
    int ty   = tid >> 2;

    ull acc[4][8];
#pragma unroll
    for (int p = 0; p < 4; p++)
#pragma unroll
        for (int c = 0; c < 8; c++) acc[p][c] = 0ull;

    for (int kc = 0; kc < H1; kc += G2_KC) {
#pragma unroll
        for (int j = 0; j < 8; j++) {
            int i = tid + j * 128;
            int r = i >> 2, kq = i & 3;
            int row = row0 + r;
            float4 v = make_float4(0.f, 0.f, 0.f, 0.f);
            if (row < N_NODES)
                v = *reinterpret_cast<const float4*>(&g_a1[(size_t)row * H1 + kc + kq * 4]);
            sXt[(kq * 4 + 0) * G1_XP + r] = v.x;
            sXt[(kq * 4 + 1) * G1_XP + r] = v.y;
            sXt[(kq * 4 + 2) * G1_XP + r] = v.z;
            sXt[(kq * 4 + 3) * G1_XP + r] = v.w;
        }
#pragma unroll
        for (int j = 0; j < 4; j++) {
            int i = tid + j * 128;
            int k = i >> 5, c = i & 31;
            sW2[k * H2 + c] = bcast2(W2[(size_t)(kc + k) * H2 + c]);
        }
        __syncthreads();
#pragma unroll
        for (int k = 0; k < G2_KC; k++) {
            const ull* xk = reinterpret_cast<const ull*>(&sXt[k * G1_XP + ty * 8]);
            ull x0 = xk[0], x1 = xk[1], x2 = xk[2], x3 = xk[3];
            const ull* wk = &sW2[k * H2 + tx * 8];
#pragma unroll
            for (int c = 0; c < 8; c++) {
                ull wb = wk[c];
                fma2(acc[0][c], x0, wb);
                fma2(acc[1][c], x1, wb);
                fma2(acc[2][c], x2, wb);
                fma2(acc[3][c], x3, wb);
            }
        }
        __syncthreads();
    }
#pragma unroll
    for (int p = 0; p < 4; p++) {
#pragma unroll
        for (int h = 0; h < 2; h++) {
            int row = row0 + ty * 8 + 2 * p + h;
            if (row < N_NODES) {
                float o[8];
#pragma unroll
                for (int c = 0; c < 8; c++) {
                    unsigned v = h ? (unsigned)(acc[p][c] >> 32) : (unsigned)acc[p][c];
                    o[c] = __uint_as_float(v);
                }
                float4* dst4 = reinterpret_cast<float4*>(&g_h2[(size_t)row * H2 + tx * 8]);
                dst4[0] = make_float4(o[0], o[1], o[2], o[3]);
                dst4[1] = make_float4(o[4], o[5], o[6], o[7]);
            }
        }
    }
}

// ---------------- aggregation 2: out = sum_e w*h2[src] ---------------------
__global__ __launch_bounds__(256) void agg2_kernel(float* __restrict__ out) {
    int node = blockIdx.x * 8 + (threadIdx.x >> 5);
    if (node >= N_NODES) return;
    int lane = threadIdx.x & 31;
    int p = g_off[node], e = g_off[node + 1];
    float a0 = 0.f, a1v = 0.f;
    for (; p + 4 <= e; p += 4) {
        int2 r0 = g_edge[p + 0];
        int2 r1 = g_edge[p + 1];
        int2 r2 = g_edge[p + 2];
        int2 r3 = g_edge[p + 3];
        float v0 = g_h2[(size_t)r0.x * H2 + lane];
        float v1 = g_h2[(size_t)r1.x * H2 + lane];
        float v2 = g_h2[(size_t)r2.x * H2 + lane];
        float v3 = g_h2[(size_t)r3.x * H2 + lane];
        a0  = fmaf(__int_as_float(r0.y), v0, a0);
        a1v = fmaf(__int_as_float(r1.y), v1, a1v);
        a0  = fmaf(__int_as_float(r2.y), v2, a0);
        a1v = fmaf(__int_as_float(r3.y), v3, a1v);
    }
    for (; p < e; p++) {
        int2 r = g_edge[p];
        a0 = fmaf(__int_as_float(r.y), g_h2[(size_t)r.x * H2 + lane], a0);
    }
    out[(size_t)node * H2 + lane] = a0 + a1v;
}

// ---------------- launch: CSR build forked parallel to gemm1 ---------------
extern "C" void kernel_launch(void* const* d_in, const int* in_sizes, int n_in,
                              void* d_out, int out_size) {
    const float* features = (const float*)d_in[0];
    const float* ew       = (const float*)d_in[1];
    const float* W1       = (const float*)d_in[2];
    const float* W2       = (const float*)d_in[3];
    const int*   src      = (const int*)d_in[4];
    const int*   dst      = (const int*)d_in[5];
    float*       out      = (float*)d_out;

    cudaStream_t s2 = 0;
    cudaEvent_t  e0 = 0, e1 = 0;
    bool fork =
        (cudaStreamCreateWithFlags(&s2, cudaStreamNonBlocking) == cudaSuccess) &&
        (cudaEventCreateWithFlags(&e0, cudaEventDisableTiming) == cudaSuccess) &&
        (cudaEventCreateWithFlags(&e1, cudaEventDisableTiming) == cudaSuccess);
    cudaStream_t sb = fork ? s2 : (cudaStream_t)0;

    if (fork) {
        cudaEventRecord(e0, 0);            // fork from capture (default) stream
        cudaStreamWaitEvent(s2, e0, 0);
    }

    // --- build chain on side stream ---
    zero_deg_kernel<<<SCAN_B, 256, 0, sb>>>();
    count_kernel<<<(N_EDGES + 255) / 256, 256, 0, sb>>>(dst);
    scan1_kernel<<<SCAN_B, 256, 0, sb>>>();
    scan2_kernel<<<1, 512, 0, sb>>>();
    scan3_kernel<<<SCAN_B, 256, 0, sb>>>();
    fill_kernel<<<(N_EDGES + 255) / 256, 256, 0, sb>>>(ew, src, dst);

    // --- gemm1 concurrently on main stream ---
    gemm1_kernel<<<(N_NODES + 255) / 256, 256>>>(features, W1);

    if (fork) {
        cudaEventRecord(e1, s2);           // join build into main stream
        cudaStreamWaitEvent(0, e1, 0);
    }

    agg1_kernel<<<(N_NODES + 7) / 8, 256>>>();
    gemm2_kernel<<<(N_NODES + 255) / 256, 128>>>(W2);
    agg2_kernel<<<(N_NODES + 7) / 8, 256>>>(out);
}